// round 11
// baseline (speedup 1.0000x reference)
#include <cuda_runtime.h>
#include <math.h>

#define N_NODES 100000
#define N_EDGES 1600000
#define D 128
#define KC 32   // K-chunk for GEMM smem staging

// ---------------- static device scratch (no allocations allowed) ----------------
__device__ int    g_is64;                     // 1 if edge_index is int64, 0 if int32
__device__ int    g_deg[N_NODES];
__device__ int    g_off[N_NODES];
__device__ int    g_cur[N_NODES];
__device__ float  g_dis[N_NODES];             // deg^-1/2
__device__ int    g_scol[N_EDGES];            // edge cols grouped by dest row
__device__ float4 g_h4[(size_t)N_NODES * 32]; // x @ neighbor_weight, 16B-aligned
__device__ int    g_bsum[128];

__device__ __forceinline__ int clampN(int v) {
    v = v < 0 ? 0 : v;
    return v >= N_NODES ? N_NODES - 1 : v;
}

// ---------------- zero degrees + dtype detection (fused) ----------------
// int64 little-endian values in [0, N_NODES) have all-zero high words.
// int32 data at odd word positions is a random index (zero w.p. 1e-5 each).
__global__ void k_zero_detect(const unsigned int* __restrict__ w) {
    int i = blockIdx.x * blockDim.x + threadIdx.x;
    if (i < N_NODES) g_deg[i] = 0;
    if (i == 0) {
        int is64 = 1;
        for (int j = 0; j < 64; j++)
            if (w[2 * j + 1] != 0u) { is64 = 0; break; }
        g_is64 = is64;
    }
}

// ---------------- degree count: 4 edges per thread, vector loads ----------------
__global__ void k_count(const void* __restrict__ eidx) {
    int q = blockIdx.x * blockDim.x + threadIdx.x;   // quad index
    if (q < N_EDGES / 4) {
        int r0, r1, r2, r3;
        if (g_is64) {
            longlong4 v = ((const longlong4*)eidx)[q];
            r0 = (int)v.x; r1 = (int)v.y; r2 = (int)v.z; r3 = (int)v.w;
        } else {
            int4 v = ((const int4*)eidx)[q];
            r0 = v.x; r1 = v.y; r2 = v.z; r3 = v.w;
        }
        atomicAdd(&g_deg[clampN(r0)], 1);
        atomicAdd(&g_deg[clampN(r1)], 1);
        atomicAdd(&g_deg[clampN(r2)], 1);
        atomicAdd(&g_deg[clampN(r3)], 1);
    }
}

// block-wise exclusive scan of g_deg (98 blocks x 1024)
__global__ void k_scanA() {
    __shared__ int s[1024];
    int tid = threadIdx.x;
    int i = blockIdx.x * 1024 + tid;
    int v = (i < N_NODES) ? g_deg[i] : 0;
    s[tid] = v;
    __syncthreads();
    for (int d = 1; d < 1024; d <<= 1) {
        int t = (tid >= d) ? s[tid - d] : 0;
        __syncthreads();
        s[tid] += t;
        __syncthreads();
    }
    if (i < N_NODES) g_off[i] = s[tid] - v;   // exclusive within block
    if (tid == 1023) g_bsum[blockIdx.x] = s[1023];
}

// scanC with inlined cross-block prefix (replaces serial k_scanB):
// each block tree-reduces g_bsum[0..blockIdx.x) with 128 threads.
__global__ void k_scanC() {
    __shared__ int red[128];
    int tid = threadIdx.x;
    if (tid < 128) red[tid] = (tid < blockIdx.x) ? g_bsum[tid] : 0; // blockIdx<=97
    __syncthreads();
#pragma unroll
    for (int d = 64; d > 0; d >>= 1) {
        if (tid < d) red[tid] += red[tid + d];
        __syncthreads();
    }
    int base = red[0];
    int i = blockIdx.x * 1024 + tid;
    if (i < N_NODES) {
        int o = g_off[i] + base;
        g_off[i] = o;
        g_cur[i] = o;
        g_dis[i] = rsqrtf((float)g_deg[i]);   // deg==0 -> inf, matches deg**-0.5
    }
}

// ---------------- scatter: 4 edges per thread, vector loads ----------------
__global__ void k_scatter(const void* __restrict__ eidx) {
    int q = blockIdx.x * blockDim.x + threadIdx.x;
    if (q < N_EDGES / 4) {
        int r[4], c[4];
        if (g_is64) {
            const longlong4* rp = (const longlong4*)eidx;
            const longlong4* cp = (const longlong4*)((const long long*)eidx + N_EDGES);
            longlong4 rv = rp[q], cv = cp[q];
            r[0] = (int)rv.x; r[1] = (int)rv.y; r[2] = (int)rv.z; r[3] = (int)rv.w;
            c[0] = (int)cv.x; c[1] = (int)cv.y; c[2] = (int)cv.z; c[3] = (int)cv.w;
        } else {
            const int4* rp = (const int4*)eidx;
            const int4* cp = (const int4*)((const int*)eidx + N_EDGES);
            int4 rv = rp[q], cv = cp[q];
            r[0] = rv.x; r[1] = rv.y; r[2] = rv.z; r[3] = rv.w;
            c[0] = cv.x; c[1] = cv.y; c[2] = cv.z; c[3] = cv.w;
        }
#pragma unroll
        for (int j = 0; j < 4; j++) {
            int pos = atomicAdd(&g_cur[clampN(r[j])], 1);
            g_scol[pos] = clampN(c[j]);
        }
    }
}

// ---------------- packed f32x2 FMA helpers (Blackwell) ----------------
__device__ __forceinline__ void fma2(unsigned long long& acc,
                                     unsigned long long a,
                                     unsigned long long b) {
    asm("fma.rn.f32x2 %0, %1, %2, %0;" : "+l"(acc) : "l"(a), "l"(b));
}
__device__ __forceinline__ unsigned long long dup2(float v) {
    unsigned long long p;
    asm("mov.b64 %0, {%1, %1};" : "=l"(p) : "f"(v));
    return p;
}
__device__ __forceinline__ float2 unpk2(unsigned long long v) {
    float lo, hi;
    asm("mov.b64 {%0, %1}, %2;" : "=f"(lo), "=f"(hi) : "l"(v));
    return make_float2(lo, hi);
}

// ---------------- fused dual GEMM: out = x@Ws + bias, g_h = x@Wn ----------------
// Tile: 128 rows x (128+128) cols, 512 threads (16 warps), K chunked by 32.
// Static smem = 3 * 32*128 * 4B = 48 KB.
__global__ void __launch_bounds__(512)
k_gemm(const float* __restrict__ x,
       const float* __restrict__ Ws,
       const float* __restrict__ Wn,
       const float* __restrict__ bias,
       float* __restrict__ out) {
    __shared__ float sWs[KC * D];   // [kk][c]
    __shared__ float sWn[KC * D];   // [kk][c]
    __shared__ float sX [D * KC];   // [r][kk]

    int tid = threadIdx.x;
    int rowBase = blockIdx.x * 128;
    int warp = tid >> 5;
    int lane = tid & 31;
    int rb = warp * 8;
    int cb = lane * 4;

    unsigned long long accS[8][2], accN[8][2];
#pragma unroll
    for (int i = 0; i < 8; i++) {
        accS[i][0] = 0ull; accS[i][1] = 0ull;
        accN[i][0] = 0ull; accN[i][1] = 0ull;
    }

    for (int kc = 0; kc < D; kc += KC) {
        __syncthreads();   // protect previous chunk's reads
        {
            const float4* a = (const float4*)(Ws + kc * D);
            const float4* b = (const float4*)(Wn + kc * D);
            float4* sa = (float4*)sWs;
            float4* sb = (float4*)sWn;
            for (int i = tid; i < KC * D / 4; i += 512) { sa[i] = a[i]; sb[i] = b[i]; }
        }
        for (int i = tid; i < 128 * (KC / 4); i += 512) {
            int r = i >> 3;
            int q = i & 7;
            int gr = rowBase + r;
            float4 v = (gr < N_NODES)
                ? ((const float4*)x)[(size_t)gr * (D / 4) + (kc / 4) + q]
                : make_float4(0.f, 0.f, 0.f, 0.f);
            ((float4*)sX)[r * (KC / 4) + q] = v;
        }
        __syncthreads();

#pragma unroll 4
        for (int kk = 0; kk < KC; kk++) {
            ulonglong2 wa = *(const ulonglong2*)&sWs[kk * D + cb];
            ulonglong2 wb = *(const ulonglong2*)&sWn[kk * D + cb];
#pragma unroll
            for (int i = 0; i < 8; i++) {
                unsigned long long xv = dup2(sX[(rb + i) * KC + kk]); // bcast LDS
                fma2(accS[i][0], xv, wa.x);
                fma2(accS[i][1], xv, wa.y);
                fma2(accN[i][0], xv, wb.x);
                fma2(accN[i][1], xv, wb.y);
            }
        }
    }

    float4 bv = ((const float4*)bias)[lane];
#pragma unroll
    for (int i = 0; i < 8; i++) {
        int gr = rowBase + rb + i;
        if (gr < N_NODES) {
            float2 s0 = unpk2(accS[i][0]);
            float2 s1 = unpk2(accS[i][1]);
            float4 o;
            o.x = s0.x + bv.x; o.y = s0.y + bv.y;
            o.z = s1.x + bv.z; o.w = s1.y + bv.w;
            ((float4*)out)[(size_t)gr * 32 + lane] = o;
            float2 n0 = unpk2(accN[i][0]);
            float2 n1 = unpk2(accN[i][1]);
            float4 hh;
            hh.x = n0.x; hh.y = n0.y; hh.z = n1.x; hh.w = n1.y;
            g_h4[(size_t)gr * 32 + lane] = hh;
        }
    }
}

// ---------------- SpMM: one warp per row, gather-accumulate (no atomics) --------
__global__ void __launch_bounds__(256)
k_spmm(float* __restrict__ out) {
    int gw = (blockIdx.x * blockDim.x + threadIdx.x) >> 5;
    int lane = threadIdx.x & 31;
    if (gw >= N_NODES) return;
    int r = gw;
    int beg = g_off[r];
    int cnt = g_deg[r];
    float disr = g_dis[r];

    float ax = 0.f, ay = 0.f, az = 0.f, aw = 0.f;
    int e = 0;
    for (; e + 1 < cnt; e += 2) {
        int c0 = g_scol[beg + e];
        int c1 = g_scol[beg + e + 1];
        float n0 = disr * g_dis[c0];
        float n1 = disr * g_dis[c1];
        float4 h0 = g_h4[(size_t)c0 * 32 + lane];
        float4 h1 = g_h4[(size_t)c1 * 32 + lane];
        ax += n0 * h0.x + n1 * h1.x;
        ay += n0 * h0.y + n1 * h1.y;
        az += n0 * h0.z + n1 * h1.z;
        aw += n0 * h0.w + n1 * h1.w;
    }
    if (e < cnt) {
        int c = g_scol[beg + e];
        float nrm = disr * g_dis[c];
        float4 hv = g_h4[(size_t)c * 32 + lane];
        ax += nrm * hv.x; ay += nrm * hv.y;
        az += nrm * hv.z; aw += nrm * hv.w;
    }
    float4* op = (float4*)out + (size_t)r * 32 + lane;
    float4 o = *op;               // already holds self_support + bias
    o.x += ax; o.y += ay; o.z += az; o.w += aw;
    *op = o;
}

// ---------------- launch: fork preprocessing parallel to GEMM ----------------
extern "C" void kernel_launch(void* const* d_in, const int* in_sizes, int n_in,
                              void* d_out, int out_size) {
    const float* x    = (const float*)d_in[0];
    const void*  eidx = d_in[1];                 // int32 or int64 — detected on device
    const float* Ws   = (const float*)d_in[2];
    const float* Wn   = (const float*)d_in[3];
    const float* bias = (const float*)d_in[4];
    float*       out  = (float*)d_out;

    // fork-join: GEMM (compute-bound, ~190us) on the origin stream, the
    // memory-bound CSR-build chain (~45us) concurrently on a side stream.
    // Kernel launches + event record/wait only — graph-capture legal.
    cudaStream_t sPre;
    cudaStreamCreateWithFlags(&sPre, cudaStreamNonBlocking);
    cudaEvent_t evFork, evJoin;
    cudaEventCreateWithFlags(&evFork, cudaEventDisableTiming);
    cudaEventCreateWithFlags(&evJoin, cudaEventDisableTiming);

    cudaEventRecord(evFork, 0);
    cudaStreamWaitEvent(sPre, evFork, 0);

    k_zero_detect<<<(N_NODES + 255) / 256, 256, 0, sPre>>>((const unsigned int*)eidx);
    k_count<<<(N_EDGES / 4 + 255) / 256, 256, 0, sPre>>>(eidx);
    k_scanA<<<98, 1024, 0, sPre>>>();
    k_scanC<<<98, 1024, 0, sPre>>>();
    k_scatter<<<(N_EDGES / 4 + 255) / 256, 256, 0, sPre>>>(eidx);
    cudaEventRecord(evJoin, sPre);

    k_gemm<<<(N_NODES + 127) / 128, 512>>>(x, Ws, Wn, bias, out);
    cudaStreamWaitEvent(0, evJoin, 0);
    k_spmm<<<(N_NODES * 32 + 255) / 256, 256>>>(out);
    // handles intentionally not destroyed during capture (capture-unsafe);
    // a few leaked host handles across the harness's handful of calls is benign.
}

// round 12
// speedup vs baseline: 1.7484x; 1.7484x over previous
#include <cuda_runtime.h>
#include <math.h>

#define N_NODES 100000
#define N_EDGES 1600000
#define D 128
#define KC 32   // K-chunk for GEMM smem staging

// ---------------- static device scratch (no allocations allowed) ----------------
__device__ int    g_is64;                     // 1 if edge_index is int64, 0 if int32
__device__ int    g_deg[N_NODES];
__device__ int    g_off[N_NODES];
__device__ int    g_cur[N_NODES];
__device__ float  g_dis[N_NODES];             // deg^-1/2
__device__ int    g_scol[N_EDGES];            // edge cols grouped by dest row
__device__ float4 g_h4[(size_t)N_NODES * 32]; // x @ neighbor_weight, 16B-aligned
__device__ int    g_bsum[128];

__device__ __forceinline__ int clampN(int v) {
    v = v < 0 ? 0 : v;
    return v >= N_NODES ? N_NODES - 1 : v;
}

// ---------------- zero degrees + dtype detection (fused) ----------------
__global__ void k_zero_detect(const unsigned int* __restrict__ w) {
    int i = blockIdx.x * blockDim.x + threadIdx.x;
    if (i < N_NODES) g_deg[i] = 0;
    if (i == 0) {
        int is64 = 1;
        for (int j = 0; j < 64; j++)
            if (w[2 * j + 1] != 0u) { is64 = 0; break; }
        g_is64 = is64;
    }
}

// ---------------- degree count: 4 edges per thread, vector loads ----------------
__global__ void k_count(const void* __restrict__ eidx) {
    int q = blockIdx.x * blockDim.x + threadIdx.x;   // quad index
    if (q < N_EDGES / 4) {
        int r0, r1, r2, r3;
        if (g_is64) {
            longlong4 v = ((const longlong4*)eidx)[q];
            r0 = (int)v.x; r1 = (int)v.y; r2 = (int)v.z; r3 = (int)v.w;
        } else {
            int4 v = ((const int4*)eidx)[q];
            r0 = v.x; r1 = v.y; r2 = v.z; r3 = v.w;
        }
        atomicAdd(&g_deg[clampN(r0)], 1);
        atomicAdd(&g_deg[clampN(r1)], 1);
        atomicAdd(&g_deg[clampN(r2)], 1);
        atomicAdd(&g_deg[clampN(r3)], 1);
    }
}

// block-wise exclusive scan of g_deg (98 blocks x 1024)
__global__ void k_scanA() {
    __shared__ int s[1024];
    int tid = threadIdx.x;
    int i = blockIdx.x * 1024 + tid;
    int v = (i < N_NODES) ? g_deg[i] : 0;
    s[tid] = v;
    __syncthreads();
    for (int d = 1; d < 1024; d <<= 1) {
        int t = (tid >= d) ? s[tid - d] : 0;
        __syncthreads();
        s[tid] += t;
        __syncthreads();
    }
    if (i < N_NODES) g_off[i] = s[tid] - v;   // exclusive within block
    if (tid == 1023) g_bsum[blockIdx.x] = s[1023];
}

// scanC with inlined cross-block prefix: tree-reduce g_bsum[0..blockIdx.x)
__global__ void k_scanC() {
    __shared__ int red[128];
    int tid = threadIdx.x;
    if (tid < 128) red[tid] = (tid < blockIdx.x) ? g_bsum[tid] : 0; // blockIdx<=97
    __syncthreads();
#pragma unroll
    for (int d = 64; d > 0; d >>= 1) {
        if (tid < d) red[tid] += red[tid + d];
        __syncthreads();
    }
    int base = red[0];
    int i = blockIdx.x * 1024 + tid;
    if (i < N_NODES) {
        int o = g_off[i] + base;
        g_off[i] = o;
        g_cur[i] = o;
        g_dis[i] = rsqrtf((float)g_deg[i]);   // deg==0 -> inf, matches deg**-0.5
    }
}

// ---------------- scatter: 4 edges per thread, vector loads ----------------
__global__ void k_scatter(const void* __restrict__ eidx) {
    int q = blockIdx.x * blockDim.x + threadIdx.x;
    if (q < N_EDGES / 4) {
        int r[4], c[4];
        if (g_is64) {
            const longlong4* rp = (const longlong4*)eidx;
            const longlong4* cp = (const longlong4*)((const long long*)eidx + N_EDGES);
            longlong4 rv = rp[q], cv = cp[q];
            r[0] = (int)rv.x; r[1] = (int)rv.y; r[2] = (int)rv.z; r[3] = (int)rv.w;
            c[0] = (int)cv.x; c[1] = (int)cv.y; c[2] = (int)cv.z; c[3] = (int)cv.w;
        } else {
            const int4* rp = (const int4*)eidx;
            const int4* cp = (const int4*)((const int*)eidx + N_EDGES);
            int4 rv = rp[q], cv = cp[q];
            r[0] = rv.x; r[1] = rv.y; r[2] = rv.z; r[3] = rv.w;
            c[0] = cv.x; c[1] = cv.y; c[2] = cv.z; c[3] = cv.w;
        }
#pragma unroll
        for (int j = 0; j < 4; j++) {
            int pos = atomicAdd(&g_cur[clampN(r[j])], 1);
            g_scol[pos] = clampN(c[j]);
        }
    }
}

// ---------------- TF32 tensor-core dual GEMM ----------------
// out = x@Ws + bias (warps 0-7), g_h = x@Wn (warps 8-15).
// Block: 128 rows, 512 threads. Each warp: 32 rows x 64 cols of its matrix
// = 2 m-tiles x 8 n-tiles of m16n8k8 mma.sync, K chunked by 32 via SMEM.
#define XS 36    // sX row stride: bank = (4r+kk)%32, conflict-free frag loads
#define WS 136   // sW row stride: bank = (8kk+n)%32, conflict-free frag loads

__device__ __forceinline__ unsigned int f2tf32(float f) {
    unsigned int u;
    asm("cvt.rna.tf32.f32 %0, %1;" : "=r"(u) : "f"(f));
    return u;
}

__device__ __forceinline__ void mma_tf32(float* d, const unsigned int* a,
                                         unsigned int b0, unsigned int b1) {
    asm("mma.sync.aligned.m16n8k8.row.col.f32.tf32.tf32.f32 "
        "{%0,%1,%2,%3}, {%4,%5,%6,%7}, {%8,%9}, {%0,%1,%2,%3};"
        : "+f"(d[0]), "+f"(d[1]), "+f"(d[2]), "+f"(d[3])
        : "r"(a[0]), "r"(a[1]), "r"(a[2]), "r"(a[3]), "r"(b0), "r"(b1));
}

__global__ void __launch_bounds__(512)
k_gemm(const float* __restrict__ x,
       const float* __restrict__ Ws,
       const float* __restrict__ Wn,
       const float* __restrict__ bias,
       float* __restrict__ out) {
    __shared__ unsigned int sW[2 * KC * WS];  // [mat][kk][c], tf32 bits
    __shared__ unsigned int sX[128 * XS];     // [r][kk], tf32 bits

    int tid = threadIdx.x;
    int rowBase = blockIdx.x * 128;
    int warp = tid >> 5;
    int lane = tid & 31;
    int mat = warp >> 3;          // 0 = self(Ws->out), 1 = neighbor(Wn->g_h)
    int ww = warp & 7;
    int rowOff = (ww >> 1) * 32;  // 0,32,64,96
    int colOff = (ww & 1) * 64;   // 0,64
    int grp = lane >> 2;          // 0..7
    int tg = lane & 3;            // 0..3

    float acc[2][8][4];
#pragma unroll
    for (int mt = 0; mt < 2; mt++)
#pragma unroll
        for (int j = 0; j < 8; j++)
#pragma unroll
            for (int q = 0; q < 4; q++) acc[mt][j][q] = 0.f;

    for (int kc = 0; kc < D; kc += KC) {
        __syncthreads();   // protect previous chunk's reads
        // stage both weight chunks as tf32 (rows [kc,kc+KC) of each)
        for (int i = tid; i < 2 * KC * D; i += 512) {
            int m = i >> 12;          // 0/1
            int j = i & 4095;
            int kk = j >> 7;
            int c = j & 127;
            float v = (m ? Wn : Ws)[(kc + kk) * D + c];
            sW[(m * KC + kk) * WS + c] = f2tf32(v);
        }
        // stage x chunk as tf32
        for (int i = tid; i < 128 * KC; i += 512) {
            int r = i >> 5;
            int kk = i & 31;
            int gr = rowBase + r;
            float v = (gr < N_NODES) ? x[(size_t)gr * D + kc + kk] : 0.f;
            sX[r * XS + kk] = f2tf32(v);
        }
        __syncthreads();

#pragma unroll
        for (int step = 0; step < KC / 8; step++) {
            int kk0 = step * 8;
            unsigned int a[2][4];
#pragma unroll
            for (int mt = 0; mt < 2; mt++) {
                int r0 = rowOff + 16 * mt + grp;
                a[mt][0] = sX[(r0)     * XS + kk0 + tg];
                a[mt][1] = sX[(r0 + 8) * XS + kk0 + tg];
                a[mt][2] = sX[(r0)     * XS + kk0 + tg + 4];
                a[mt][3] = sX[(r0 + 8) * XS + kk0 + tg + 4];
            }
            unsigned int b0[8], b1[8];
#pragma unroll
            for (int j = 0; j < 8; j++) {
                int n = colOff + 8 * j + grp;
                b0[j] = sW[(mat * KC + kk0 + tg)     * WS + n];
                b1[j] = sW[(mat * KC + kk0 + tg + 4) * WS + n];
            }
#pragma unroll
            for (int mt = 0; mt < 2; mt++)
#pragma unroll
                for (int j = 0; j < 8; j++)
                    mma_tf32(acc[mt][j], a[mt], b0[j], b1[j]);
        }
    }

    // epilogue: d0/d1 -> row grp, cols 2tg,2tg+1; d2/d3 -> row grp+8
    float* hout = (float*)g_h4;
#pragma unroll
    for (int mt = 0; mt < 2; mt++) {
#pragma unroll
        for (int j = 0; j < 8; j++) {
            int c = colOff + 8 * j + 2 * tg;
            int r0 = rowBase + rowOff + 16 * mt + grp;
            int r1 = r0 + 8;
            if (mat == 0) {
                float2 bv = *(const float2*)&bias[c];
                if (r0 < N_NODES) {
                    float2 o = make_float2(acc[mt][j][0] + bv.x, acc[mt][j][1] + bv.y);
                    *(float2*)&out[(size_t)r0 * D + c] = o;
                }
                if (r1 < N_NODES) {
                    float2 o = make_float2(acc[mt][j][2] + bv.x, acc[mt][j][3] + bv.y);
                    *(float2*)&out[(size_t)r1 * D + c] = o;
                }
            } else {
                if (r0 < N_NODES)
                    *(float2*)&hout[(size_t)r0 * D + c] =
                        make_float2(acc[mt][j][0], acc[mt][j][1]);
                if (r1 < N_NODES)
                    *(float2*)&hout[(size_t)r1 * D + c] =
                        make_float2(acc[mt][j][2], acc[mt][j][3]);
            }
        }
    }
}

// ---------------- SpMM: one warp per row, gather-accumulate (no atomics) --------
__global__ void __launch_bounds__(256)
k_spmm(float* __restrict__ out) {
    int gw = (blockIdx.x * blockDim.x + threadIdx.x) >> 5;
    int lane = threadIdx.x & 31;
    if (gw >= N_NODES) return;
    int r = gw;
    int beg = g_off[r];
    int cnt = g_deg[r];
    float disr = g_dis[r];

    float ax = 0.f, ay = 0.f, az = 0.f, aw = 0.f;
    int e = 0;
    for (; e + 1 < cnt; e += 2) {
        int c0 = g_scol[beg + e];
        int c1 = g_scol[beg + e + 1];
        float n0 = disr * g_dis[c0];
        float n1 = disr * g_dis[c1];
        float4 h0 = g_h4[(size_t)c0 * 32 + lane];
        float4 h1 = g_h4[(size_t)c1 * 32 + lane];
        ax += n0 * h0.x + n1 * h1.x;
        ay += n0 * h0.y + n1 * h1.y;
        az += n0 * h0.z + n1 * h1.z;
        aw += n0 * h0.w + n1 * h1.w;
    }
    if (e < cnt) {
        int c = g_scol[beg + e];
        float nrm = disr * g_dis[c];
        float4 hv = g_h4[(size_t)c * 32 + lane];
        ax += nrm * hv.x; ay += nrm * hv.y;
        az += nrm * hv.z; aw += nrm * hv.w;
    }
    float4* op = (float4*)out + (size_t)r * 32 + lane;
    float4 o = *op;               // already holds self_support + bias
    o.x += ax; o.y += ay; o.z += az; o.w += aw;
    *op = o;
}

// ---------------- launch: single stream (fork-join regressed in R11) ----------
extern "C" void kernel_launch(void* const* d_in, const int* in_sizes, int n_in,
                              void* d_out, int out_size) {
    const float* x    = (const float*)d_in[0];
    const void*  eidx = d_in[1];                 // int32 or int64 — detected on device
    const float* Ws   = (const float*)d_in[2];
    const float* Wn   = (const float*)d_in[3];
    const float* bias = (const float*)d_in[4];
    float*       out  = (float*)d_out;

    k_zero_detect<<<(N_NODES + 255) / 256, 256>>>((const unsigned int*)eidx);
    k_count<<<(N_EDGES / 4 + 255) / 256, 256>>>(eidx);
    k_scanA<<<98, 1024>>>();
    k_scanC<<<98, 1024>>>();
    k_scatter<<<(N_EDGES / 4 + 255) / 256, 256>>>(eidx);
    k_gemm<<<(N_NODES + 127) / 128, 512>>>(x, Ws, Wn, bias, out);
    k_spmm<<<(N_NODES * 32 + 255) / 256, 256>>>(out);
}

// round 14
// speedup vs baseline: 1.8516x; 1.0590x over previous
#include <cuda_runtime.h>
#include <math.h>

#define N_NODES 100000
#define N_EDGES 1600000
#define D 128

// ---------------- static device scratch (no allocations allowed) ----------------
__device__ int    g_is64;                     // 1 if edge_index is int64, 0 if int32
__device__ int    g_deg[N_NODES];
__device__ int    g_off[N_NODES];
__device__ int    g_cur[N_NODES];
__device__ float  g_dis[N_NODES];             // deg^-1/2
__device__ int    g_scol[N_EDGES];            // edge cols grouped by dest row
__device__ float4 g_h4[(size_t)N_NODES * 32]; // x @ neighbor_weight, 16B-aligned
__device__ int    g_bsum[128];

__device__ __forceinline__ int clampN(int v) {
    v = v < 0 ? 0 : v;
    return v >= N_NODES ? N_NODES - 1 : v;
}

// ---------------- zero degrees + dtype detection (fused) ----------------
__global__ void k_zero_detect(const unsigned int* __restrict__ w) {
    int i = blockIdx.x * blockDim.x + threadIdx.x;
    if (i < N_NODES) g_deg[i] = 0;
    if (i == 0) {
        int is64 = 1;
        for (int j = 0; j < 64; j++)
            if (w[2 * j + 1] != 0u) { is64 = 0; break; }
        g_is64 = is64;
    }
}

// ---------------- degree count: 4 edges per thread, vector loads ----------------
__global__ void k_count(const void* __restrict__ eidx) {
    int q = blockIdx.x * blockDim.x + threadIdx.x;   // quad index
    if (q < N_EDGES / 4) {
        int r0, r1, r2, r3;
        if (g_is64) {
            longlong4 v = ((const longlong4*)eidx)[q];
            r0 = (int)v.x; r1 = (int)v.y; r2 = (int)v.z; r3 = (int)v.w;
        } else {
            int4 v = ((const int4*)eidx)[q];
            r0 = v.x; r1 = v.y; r2 = v.z; r3 = v.w;
        }
        atomicAdd(&g_deg[clampN(r0)], 1);
        atomicAdd(&g_deg[clampN(r1)], 1);
        atomicAdd(&g_deg[clampN(r2)], 1);
        atomicAdd(&g_deg[clampN(r3)], 1);
    }
}

// block-wise exclusive scan of g_deg (98 blocks x 1024)
__global__ void k_scanA() {
    __shared__ int s[1024];
    int tid = threadIdx.x;
    int i = blockIdx.x * 1024 + tid;
    int v = (i < N_NODES) ? g_deg[i] : 0;
    s[tid] = v;
    __syncthreads();
    for (int d = 1; d < 1024; d <<= 1) {
        int t = (tid >= d) ? s[tid - d] : 0;
        __syncthreads();
        s[tid] += t;
        __syncthreads();
    }
    if (i < N_NODES) g_off[i] = s[tid] - v;   // exclusive within block
    if (tid == 1023) g_bsum[blockIdx.x] = s[1023];
}

// scanC with inlined cross-block prefix: tree-reduce g_bsum[0..blockIdx.x)
__global__ void k_scanC() {
    __shared__ int red[128];
    int tid = threadIdx.x;
    if (tid < 128) red[tid] = (tid < blockIdx.x) ? g_bsum[tid] : 0; // blockIdx<=97
    __syncthreads();
#pragma unroll
    for (int d = 64; d > 0; d >>= 1) {
        if (tid < d) red[tid] += red[tid + d];
        __syncthreads();
    }
    int base = red[0];
    int i = blockIdx.x * 1024 + tid;
    if (i < N_NODES) {
        int o = g_off[i] + base;
        g_off[i] = o;
        g_cur[i] = o;
        g_dis[i] = rsqrtf((float)g_deg[i]);   // deg==0 -> inf, matches deg**-0.5
    }
}

// ---------------- scatter: 4 edges per thread, vector loads ----------------
__global__ void k_scatter(const void* __restrict__ eidx) {
    int q = blockIdx.x * blockDim.x + threadIdx.x;
    if (q < N_EDGES / 4) {
        int r[4], c[4];
        if (g_is64) {
            const longlong4* rp = (const longlong4*)eidx;
            const longlong4* cp = (const longlong4*)((const long long*)eidx + N_EDGES);
            longlong4 rv = rp[q], cv = cp[q];
            r[0] = (int)rv.x; r[1] = (int)rv.y; r[2] = (int)rv.z; r[3] = (int)rv.w;
            c[0] = (int)cv.x; c[1] = (int)cv.y; c[2] = (int)cv.z; c[3] = (int)cv.w;
        } else {
            const int4* rp = (const int4*)eidx;
            const int4* cp = (const int4*)((const int*)eidx + N_EDGES);
            int4 rv = rp[q], cv = cp[q];
            r[0] = rv.x; r[1] = rv.y; r[2] = rv.z; r[3] = rv.w;
            c[0] = cv.x; c[1] = cv.y; c[2] = cv.z; c[3] = cv.w;
        }
#pragma unroll
        for (int j = 0; j < 4; j++) {
            int pos = atomicAdd(&g_cur[clampN(r[j])], 1);
            g_scol[pos] = clampN(c[j]);
        }
    }
}

// ---------------- TF32 tensor-core dual GEMM, fully SMEM-resident weights ------
// out = x@Ws + bias (warps 0-7), g_h = x@Wn (warps 8-15).
// Block: 128 rows, 512 threads. Each warp: 32 rows x 64 cols of its matrix
// = 2 m-tiles x 8 n-tiles of m16n8k8 mma.sync over the full K=128.
// SMEM: sW 2*128*136*4 = 139.3KB + sX 128*132*4 = 67.6KB = 202KB (dynamic).
#define XS 132   // sX row stride: bank = (4*row + k)%32, conflict-free frag loads
#define WS 136   // sW row stride: bank = (8*k + n)%32, conflict-free frag loads
#define GEMM_SMEM ((2 * 128 * WS + 128 * XS) * 4)

__device__ __forceinline__ unsigned int f2tf32(float f) {
    unsigned int u;
    asm("cvt.rna.tf32.f32 %0, %1;" : "=r"(u) : "f"(f));
    return u;
}

__device__ __forceinline__ void mma_tf32(float* d, const unsigned int* a,
                                         unsigned int b0, unsigned int b1) {
    asm("mma.sync.aligned.m16n8k8.row.col.f32.tf32.tf32.f32 "
        "{%0,%1,%2,%3}, {%4,%5,%6,%7}, {%8,%9}, {%0,%1,%2,%3};"
        : "+f"(d[0]), "+f"(d[1]), "+f"(d[2]), "+f"(d[3])
        : "r"(a[0]), "r"(a[1]), "r"(a[2]), "r"(a[3]), "r"(b0), "r"(b1));
}

__global__ void __launch_bounds__(512)
k_gemm(const float* __restrict__ x,
       const float* __restrict__ Ws,
       const float* __restrict__ Wn,
       const float* __restrict__ bias,
       float* __restrict__ out) {
    extern __shared__ unsigned int smem[];
    unsigned int* sW = smem;                 // [mat][k][c] tf32 bits
    unsigned int* sX = smem + 2 * 128 * WS;  // [r][k]     tf32 bits

    int tid = threadIdx.x;
    int rowBase = blockIdx.x * 128;
    int warp = tid >> 5;
    int lane = tid & 31;
    int mat = warp >> 3;          // 0 = self(Ws->out), 1 = neighbor(Wn->g_h)
    int ww = warp & 7;
    int rowOff = (ww >> 1) * 32;  // 0,32,64,96
    int colOff = (ww & 1) * 64;   // 0,64
    int grp = lane >> 2;          // 0..7
    int tg = lane & 3;            // 0..3

    // ---- stage both full weight matrices as tf32 (float4 loads, uint4 stores)
    for (int i = tid; i < 2 * 128 * 32; i += 512) {   // 8192 float4
        int m  = i >> 12;
        int j  = i & 4095;
        int k  = j >> 5;
        int cq = j & 31;
        float4 v = ((const float4*)(m ? Wn : Ws))[k * 32 + cq];
        *(uint4*)&sW[(m * 128 + k) * WS + cq * 4] =
            make_uint4(f2tf32(v.x), f2tf32(v.y), f2tf32(v.z), f2tf32(v.w));
    }
    // ---- stage full x tile (128 rows x 128 k)
    for (int i = tid; i < 128 * 32; i += 512) {       // 4096 float4
        int r  = i >> 5;
        int kq = i & 31;
        int gr = rowBase + r;
        float4 v = (gr < N_NODES) ? ((const float4*)x)[(size_t)gr * 32 + kq]
                                  : make_float4(0.f, 0.f, 0.f, 0.f);
        *(uint4*)&sX[r * XS + kq * 4] =
            make_uint4(f2tf32(v.x), f2tf32(v.y), f2tf32(v.z), f2tf32(v.w));
    }
    __syncthreads();

    float acc[2][8][4];
#pragma unroll
    for (int mt = 0; mt < 2; mt++)
#pragma unroll
        for (int j = 0; j < 8; j++)
#pragma unroll
            for (int q = 0; q < 4; q++) acc[mt][j][q] = 0.f;

    const unsigned int* sWm = sW + mat * 128 * WS;
#pragma unroll 4
    for (int step = 0; step < 16; step++) {
        int k0 = step * 8;
        unsigned int a[2][4];
#pragma unroll
        for (int mt = 0; mt < 2; mt++) {
            int r0 = rowOff + 16 * mt + grp;
            a[mt][0] = sX[(r0)     * XS + k0 + tg];
            a[mt][1] = sX[(r0 + 8) * XS + k0 + tg];
            a[mt][2] = sX[(r0)     * XS + k0 + tg + 4];
            a[mt][3] = sX[(r0 + 8) * XS + k0 + tg + 4];
        }
        unsigned int b0[8], b1[8];
#pragma unroll
        for (int j = 0; j < 8; j++) {
            int n = colOff + 8 * j + grp;
            b0[j] = sWm[(k0 + tg)     * WS + n];
            b1[j] = sWm[(k0 + tg + 4) * WS + n];
        }
#pragma unroll
        for (int mt = 0; mt < 2; mt++)
#pragma unroll
            for (int j = 0; j < 8; j++)
                mma_tf32(acc[mt][j], a[mt], b0[j], b1[j]);
    }

    // epilogue: d0/d1 -> row grp, cols 2tg,2tg+1; d2/d3 -> row grp+8
    float* hout = (float*)g_h4;
#pragma unroll
    for (int mt = 0; mt < 2; mt++) {
#pragma unroll
        for (int j = 0; j < 8; j++) {
            int c = colOff + 8 * j + 2 * tg;
            int r0 = rowBase + rowOff + 16 * mt + grp;
            int r1 = r0 + 8;
            if (mat == 0) {
                float2 bv = *(const float2*)&bias[c];
                if (r0 < N_NODES)
                    *(float2*)&out[(size_t)r0 * D + c] =
                        make_float2(acc[mt][j][0] + bv.x, acc[mt][j][1] + bv.y);
                if (r1 < N_NODES)
                    *(float2*)&out[(size_t)r1 * D + c] =
                        make_float2(acc[mt][j][2] + bv.x, acc[mt][j][3] + bv.y);
            } else {
                if (r0 < N_NODES)
                    *(float2*)&hout[(size_t)r0 * D + c] =
                        make_float2(acc[mt][j][0], acc[mt][j][1]);
                if (r1 < N_NODES)
                    *(float2*)&hout[(size_t)r1 * D + c] =
                        make_float2(acc[mt][j][2], acc[mt][j][3]);
            }
        }
    }
}

// ---------------- SpMM: one warp per row, gather-accumulate (no atomics) --------
__global__ void __launch_bounds__(256)
k_spmm(float* __restrict__ out) {
    int gw = (blockIdx.x * blockDim.x + threadIdx.x) >> 5;
    int lane = threadIdx.x & 31;
    if (gw >= N_NODES) return;
    int r = gw;
    int beg = g_off[r];
    int cnt = g_deg[r];
    float disr = g_dis[r];

    float ax = 0.f, ay = 0.f, az = 0.f, aw = 0.f;
    int e = 0;
    for (; e + 1 < cnt; e += 2) {
        int c0 = g_scol[beg + e];
        int c1 = g_scol[beg + e + 1];
        float n0 = disr * g_dis[c0];
        float n1 = disr * g_dis[c1];
        float4 h0 = g_h4[(size_t)c0 * 32 + lane];
        float4 h1 = g_h4[(size_t)c1 * 32 + lane];
        ax += n0 * h0.x + n1 * h1.x;
        ay += n0 * h0.y + n1 * h1.y;
        az += n0 * h0.z + n1 * h1.z;
        aw += n0 * h0.w + n1 * h1.w;
    }
    if (e < cnt) {
        int c = g_scol[beg + e];
        float nrm = disr * g_dis[c];
        float4 hv = g_h4[(size_t)c * 32 + lane];
        ax += nrm * hv.x; ay += nrm * hv.y;
        az += nrm * hv.z; aw += nrm * hv.w;
    }
    float4* op = (float4*)out + (size_t)r * 32 + lane;
    float4 o = *op;               // already holds self_support + bias
    o.x += ax; o.y += ay; o.z += az; o.w += aw;
    *op = o;
}

// ---------------- launch: single stream ----------------
extern "C" void kernel_launch(void* const* d_in, const int* in_sizes, int n_in,
                              void* d_out, int out_size) {
    const float* x    = (const float*)d_in[0];
    const void*  eidx = d_in[1];                 // int32 or int64 — detected on device
    const float* Ws   = (const float*)d_in[2];
    const float* Wn   = (const float*)d_in[3];
    const float* bias = (const float*)d_in[4];
    float*       out  = (float*)d_out;

    cudaFuncSetAttribute(k_gemm, cudaFuncAttributeMaxDynamicSharedMemorySize,
                         GEMM_SMEM);

    k_zero_detect<<<(N_NODES + 255) / 256, 256>>>((const unsigned int*)eidx);
    k_count<<<(N_EDGES / 4 + 255) / 256, 256>>>(eidx);
    k_scanA<<<98, 1024>>>();
    k_scanC<<<98, 1024>>>();
    k_scatter<<<(N_EDGES / 4 + 255) / 256, 256>>>(eidx);
    k_gemm<<<(N_NODES + 127) / 128, 512, GEMM_SMEM>>>(x, Ws, Wn, bias, out);
    k_spmm<<<(N_NODES * 32 + 255) / 256, 256>>>(out);
}

// round 15
// speedup vs baseline: 1.9562x; 1.0565x over previous
#include <cuda_runtime.h>
#include <cuda_fp16.h>
#include <math.h>

#define N_NODES 100000
#define N_EDGES 1600000
#define D 128

// ---------------- static device scratch (no allocations allowed) ----------------
__device__ int    g_is64;                     // 1 if edge_index is int64, 0 if int32
__device__ int    g_deg[N_NODES];
__device__ int    g_off[N_NODES];
__device__ int    g_cur[N_NODES];
__device__ float  g_dis[N_NODES];             // deg^-1/2
__device__ int    g_scol[N_EDGES];            // edge cols grouped by dest row
__device__ uint2  g_h2[(size_t)N_NODES * 32]; // x @ neighbor_weight, fp16 (4 halves/lane)
__device__ int    g_bsum[128];

__device__ __forceinline__ int clampN(int v) {
    v = v < 0 ? 0 : v;
    return v >= N_NODES ? N_NODES - 1 : v;
}

// ---------------- zero degrees + dtype detection (fused) ----------------
__global__ void k_zero_detect(const unsigned int* __restrict__ w) {
    int i = blockIdx.x * blockDim.x + threadIdx.x;
    if (i < N_NODES) g_deg[i] = 0;
    if (i == 0) {
        int is64 = 1;
        for (int j = 0; j < 64; j++)
            if (w[2 * j + 1] != 0u) { is64 = 0; break; }
        g_is64 = is64;
    }
}

// ---------------- degree count: 4 edges per thread, vector loads ----------------
__global__ void k_count(const void* __restrict__ eidx) {
    int q = blockIdx.x * blockDim.x + threadIdx.x;   // quad index
    if (q < N_EDGES / 4) {
        int r0, r1, r2, r3;
        if (g_is64) {
            longlong4 v = ((const longlong4*)eidx)[q];
            r0 = (int)v.x; r1 = (int)v.y; r2 = (int)v.z; r3 = (int)v.w;
        } else {
            int4 v = ((const int4*)eidx)[q];
            r0 = v.x; r1 = v.y; r2 = v.z; r3 = v.w;
        }
        atomicAdd(&g_deg[clampN(r0)], 1);
        atomicAdd(&g_deg[clampN(r1)], 1);
        atomicAdd(&g_deg[clampN(r2)], 1);
        atomicAdd(&g_deg[clampN(r3)], 1);
    }
}

// block-wise exclusive scan of g_deg (98 blocks x 1024)
__global__ void k_scanA() {
    __shared__ int s[1024];
    int tid = threadIdx.x;
    int i = blockIdx.x * 1024 + tid;
    int v = (i < N_NODES) ? g_deg[i] : 0;
    s[tid] = v;
    __syncthreads();
    for (int d = 1; d < 1024; d <<= 1) {
        int t = (tid >= d) ? s[tid - d] : 0;
        __syncthreads();
        s[tid] += t;
        __syncthreads();
    }
    if (i < N_NODES) g_off[i] = s[tid] - v;   // exclusive within block
    if (tid == 1023) g_bsum[blockIdx.x] = s[1023];
}

// scanC with inlined cross-block prefix: tree-reduce g_bsum[0..blockIdx.x)
__global__ void k_scanC() {
    __shared__ int red[128];
    int tid = threadIdx.x;
    if (tid < 128) red[tid] = (tid < blockIdx.x) ? g_bsum[tid] : 0; // blockIdx<=97
    __syncthreads();
#pragma unroll
    for (int d = 64; d > 0; d >>= 1) {
        if (tid < d) red[tid] += red[tid + d];
        __syncthreads();
    }
    int base = red[0];
    int i = blockIdx.x * 1024 + tid;
    if (i < N_NODES) {
        int o = g_off[i] + base;
        g_off[i] = o;
        g_cur[i] = o;
        g_dis[i] = rsqrtf((float)g_deg[i]);   // deg==0 -> inf, matches deg**-0.5
    }
}

// ---------------- scatter: 4 edges per thread, vector loads ----------------
__global__ void k_scatter(const void* __restrict__ eidx) {
    int q = blockIdx.x * blockDim.x + threadIdx.x;
    if (q < N_EDGES / 4) {
        int r[4], c[4];
        if (g_is64) {
            const longlong4* rp = (const longlong4*)eidx;
            const longlong4* cp = (const longlong4*)((const long long*)eidx + N_EDGES);
            longlong4 rv = rp[q], cv = cp[q];
            r[0] = (int)rv.x; r[1] = (int)rv.y; r[2] = (int)rv.z; r[3] = (int)rv.w;
            c[0] = (int)cv.x; c[1] = (int)cv.y; c[2] = (int)cv.z; c[3] = (int)cv.w;
        } else {
            const int4* rp = (const int4*)eidx;
            const int4* cp = (const int4*)((const int*)eidx + N_EDGES);
            int4 rv = rp[q], cv = cp[q];
            r[0] = rv.x; r[1] = rv.y; r[2] = rv.z; r[3] = rv.w;
            c[0] = cv.x; c[1] = cv.y; c[2] = cv.z; c[3] = cv.w;
        }
#pragma unroll
        for (int j = 0; j < 4; j++) {
            int pos = atomicAdd(&g_cur[clampN(r[j])], 1);
            g_scol[pos] = clampN(c[j]);
        }
    }
}

// ---------------- TF32 tensor-core dual GEMM, fully SMEM-resident weights ------
// out = x@Ws + bias (warps 0-7), g_h (fp16) = x@Wn (warps 8-15).
// Block: 128 rows, 512 threads. Each warp: 32 rows x 64 cols of its matrix
// = 2 m-tiles x 8 n-tiles of m16n8k8 mma.sync over the full K=128.
// SMEM: sW 2*128*136*4 = 139.3KB + sX 128*132*4 = 67.6KB = 202KB (dynamic).
#define XS 132   // sX row stride: bank = (4*row + k)%32, conflict-free frag loads
#define WS 136   // sW row stride: bank = (8*k + n)%32, conflict-free frag loads
#define GEMM_SMEM ((2 * 128 * WS + 128 * XS) * 4)

__device__ __forceinline__ unsigned int f2tf32(float f) {
    unsigned int u;
    asm("cvt.rna.tf32.f32 %0, %1;" : "=r"(u) : "f"(f));
    return u;
}

__device__ __forceinline__ void mma_tf32(float* d, const unsigned int* a,
                                         unsigned int b0, unsigned int b1) {
    asm("mma.sync.aligned.m16n8k8.row.col.f32.tf32.tf32.f32 "
        "{%0,%1,%2,%3}, {%4,%5,%6,%7}, {%8,%9}, {%0,%1,%2,%3};"
        : "+f"(d[0]), "+f"(d[1]), "+f"(d[2]), "+f"(d[3])
        : "r"(a[0]), "r"(a[1]), "r"(a[2]), "r"(a[3]), "r"(b0), "r"(b1));
}

__global__ void __launch_bounds__(512)
k_gemm(const float* __restrict__ x,
       const float* __restrict__ Ws,
       const float* __restrict__ Wn,
       const float* __restrict__ bias,
       float* __restrict__ out) {
    extern __shared__ unsigned int smem[];
    unsigned int* sW = smem;                 // [mat][k][c] tf32 bits
    unsigned int* sX = smem + 2 * 128 * WS;  // [r][k]     tf32 bits

    int tid = threadIdx.x;
    int rowBase = blockIdx.x * 128;
    int warp = tid >> 5;
    int lane = tid & 31;
    int mat = warp >> 3;          // 0 = self(Ws->out), 1 = neighbor(Wn->g_h fp16)
    int ww = warp & 7;
    int rowOff = (ww >> 1) * 32;  // 0,32,64,96
    int colOff = (ww & 1) * 64;   // 0,64
    int grp = lane >> 2;          // 0..7
    int tg = lane & 3;            // 0..3

    // ---- stage both full weight matrices as tf32 (float4 loads, uint4 stores)
    for (int i = tid; i < 2 * 128 * 32; i += 512) {   // 8192 float4
        int m  = i >> 12;
        int j  = i & 4095;
        int k  = j >> 5;
        int cq = j & 31;
        float4 v = ((const float4*)(m ? Wn : Ws))[k * 32 + cq];
        *(uint4*)&sW[(m * 128 + k) * WS + cq * 4] =
            make_uint4(f2tf32(v.x), f2tf32(v.y), f2tf32(v.z), f2tf32(v.w));
    }
    // ---- stage full x tile (128 rows x 128 k)
    for (int i = tid; i < 128 * 32; i += 512) {       // 4096 float4
        int r  = i >> 5;
        int kq = i & 31;
        int gr = rowBase + r;
        float4 v = (gr < N_NODES) ? ((const float4*)x)[(size_t)gr * 32 + kq]
                                  : make_float4(0.f, 0.f, 0.f, 0.f);
        *(uint4*)&sX[r * XS + kq * 4] =
            make_uint4(f2tf32(v.x), f2tf32(v.y), f2tf32(v.z), f2tf32(v.w));
    }
    __syncthreads();

    float acc[2][8][4];
#pragma unroll
    for (int mt = 0; mt < 2; mt++)
#pragma unroll
        for (int j = 0; j < 8; j++)
#pragma unroll
            for (int q = 0; q < 4; q++) acc[mt][j][q] = 0.f;

    const unsigned int* sWm = sW + mat * 128 * WS;
#pragma unroll 4
    for (int step = 0; step < 16; step++) {
        int k0 = step * 8;
        unsigned int a[2][4];
#pragma unroll
        for (int mt = 0; mt < 2; mt++) {
            int r0 = rowOff + 16 * mt + grp;
            a[mt][0] = sX[(r0)     * XS + k0 + tg];
            a[mt][1] = sX[(r0 + 8) * XS + k0 + tg];
            a[mt][2] = sX[(r0)     * XS + k0 + tg + 4];
            a[mt][3] = sX[(r0 + 8) * XS + k0 + tg + 4];
        }
        unsigned int b0[8], b1[8];
#pragma unroll
        for (int j = 0; j < 8; j++) {
            int n = colOff + 8 * j + grp;
            b0[j] = sWm[(k0 + tg)     * WS + n];
            b1[j] = sWm[(k0 + tg + 4) * WS + n];
        }
#pragma unroll
        for (int mt = 0; mt < 2; mt++)
#pragma unroll
            for (int j = 0; j < 8; j++)
                mma_tf32(acc[mt][j], a[mt], b0[j], b1[j]);
    }

    // epilogue: d0/d1 -> row grp, cols 2tg,2tg+1; d2/d3 -> row grp+8
    __half2* hview = (__half2*)g_h2;   // row-major: 64 half2 per row
#pragma unroll
    for (int mt = 0; mt < 2; mt++) {
#pragma unroll
        for (int j = 0; j < 8; j++) {
            int c = colOff + 8 * j + 2 * tg;
            int r0 = rowBase + rowOff + 16 * mt + grp;
            int r1 = r0 + 8;
            if (mat == 0) {
                float2 bv = *(const float2*)&bias[c];
                if (r0 < N_NODES)
                    *(float2*)&out[(size_t)r0 * D + c] =
                        make_float2(acc[mt][j][0] + bv.x, acc[mt][j][1] + bv.y);
                if (r1 < N_NODES)
                    *(float2*)&out[(size_t)r1 * D + c] =
                        make_float2(acc[mt][j][2] + bv.x, acc[mt][j][3] + bv.y);
            } else {
                if (r0 < N_NODES)
                    hview[(size_t)r0 * 64 + (c >> 1)] =
                        __floats2half2_rn(acc[mt][j][0], acc[mt][j][1]);
                if (r1 < N_NODES)
                    hview[(size_t)r1 * 64 + (c >> 1)] =
                        __floats2half2_rn(acc[mt][j][2], acc[mt][j][3]);
            }
        }
    }
}

// ---------------- SpMM: one warp per row, fp16 gather-accumulate (no atomics) ---
__global__ void __launch_bounds__(256)
k_spmm(float* __restrict__ out) {
    int gw = (blockIdx.x * blockDim.x + threadIdx.x) >> 5;
    int lane = threadIdx.x & 31;
    if (gw >= N_NODES) return;
    int r = gw;
    int beg = g_off[r];
    int cnt = g_deg[r];
    float disr = g_dis[r];

    float ax = 0.f, ay = 0.f, az = 0.f, aw = 0.f;
    int e = 0;
    for (; e + 1 < cnt; e += 2) {
        int c0 = g_scol[beg + e];
        int c1 = g_scol[beg + e + 1];
        float n0 = disr * g_dis[c0];
        float n1 = disr * g_dis[c1];
        uint2 v0 = g_h2[(size_t)c0 * 32 + lane];   // 4 halves = cols 4*lane..+3
        uint2 v1 = g_h2[(size_t)c1 * 32 + lane];
        float2 h0a = __half22float2(*(__half2*)&v0.x);
        float2 h0b = __half22float2(*(__half2*)&v0.y);
        float2 h1a = __half22float2(*(__half2*)&v1.x);
        float2 h1b = __half22float2(*(__half2*)&v1.y);
        ax += n0 * h0a.x + n1 * h1a.x;
        ay += n0 * h0a.y + n1 * h1a.y;
        az += n0 * h0b.x + n1 * h1b.x;
        aw += n0 * h0b.y + n1 * h1b.y;
    }
    if (e < cnt) {
        int c = g_scol[beg + e];
        float nrm = disr * g_dis[c];
        uint2 v = g_h2[(size_t)c * 32 + lane];
        float2 ha = __half22float2(*(__half2*)&v.x);
        float2 hb = __half22float2(*(__half2*)&v.y);
        ax += nrm * ha.x; ay += nrm * ha.y;
        az += nrm * hb.x; aw += nrm * hb.y;
    }
    float4* op = (float4*)out + (size_t)r * 32 + lane;
    float4 o = *op;               // already holds self_support + bias
    o.x += ax; o.y += ay; o.z += az; o.w += aw;
    *op = o;
}

// ---------------- launch: single stream ----------------
extern "C" void kernel_launch(void* const* d_in, const int* in_sizes, int n_in,
                              void* d_out, int out_size) {
    const float* x    = (const float*)d_in[0];
    const void*  eidx = d_in[1];                 // int32 or int64 — detected on device
    const float* Ws   = (const float*)d_in[2];
    const float* Wn   = (const float*)d_in[3];
    const float* bias = (const float*)d_in[4];
    float*       out  = (float*)d_out;

    cudaFuncSetAttribute(k_gemm, cudaFuncAttributeMaxDynamicSharedMemorySize,
                         GEMM_SMEM);

    k_zero_detect<<<(N_NODES + 255) / 256, 256>>>((const unsigned int*)eidx);
    k_count<<<(N_EDGES / 4 + 255) / 256, 256>>>(eidx);
    k_scanA<<<98, 1024>>>();
    k_scanC<<<98, 1024>>>();
    k_scatter<<<(N_EDGES / 4 + 255) / 256, 256>>>(eidx);
    k_gemm<<<(N_NODES + 127) / 128, 512, GEMM_SMEM>>>(x, Ws, Wn, bias, out);
    k_spmm<<<(N_NODES * 32 + 255) / 256, 256>>>(out);
}

// round 16
// speedup vs baseline: 2.2305x; 1.1402x over previous
#include <cuda_runtime.h>
#include <cuda_fp16.h>
#include <math.h>

#define N_NODES 100000
#define N_EDGES 1600000
#define D 128

// ---------------- static device scratch (no allocations allowed) ----------------
__device__ int    g_is64;                     // 1 if edge_index is int64, 0 if int32
__device__ int    g_deg[N_NODES];
__device__ int    g_off[N_NODES];
__device__ int    g_cur[N_NODES];
__device__ float  g_dis[N_NODES];             // deg^-1/2
__device__ int    g_scol[N_EDGES];            // edge cols grouped by dest row
__device__ uint2  g_h2[(size_t)N_NODES * 32]; // x @ neighbor_weight, fp16 (4 halves/lane)
__device__ int    g_bsum[128];

__device__ __forceinline__ int clampN(int v) {
    v = v < 0 ? 0 : v;
    return v >= N_NODES ? N_NODES - 1 : v;
}

// ---------------- zero degrees + dtype detection (fused) ----------------
__global__ void k_zero_detect(const unsigned int* __restrict__ w) {
    int i = blockIdx.x * blockDim.x + threadIdx.x;
    if (i < N_NODES) g_deg[i] = 0;
    if (i == 0) {
        int is64 = 1;
        for (int j = 0; j < 64; j++)
            if (w[2 * j + 1] != 0u) { is64 = 0; break; }
        g_is64 = is64;
    }
}

// ---------------- degree count: 4 edges per thread, vector loads ----------------
__global__ void k_count(const void* __restrict__ eidx) {
    int q = blockIdx.x * blockDim.x + threadIdx.x;   // quad index
    if (q < N_EDGES / 4) {
        int r0, r1, r2, r3;
        if (g_is64) {
            longlong4 v = ((const longlong4*)eidx)[q];
            r0 = (int)v.x; r1 = (int)v.y; r2 = (int)v.z; r3 = (int)v.w;
        } else {
            int4 v = ((const int4*)eidx)[q];
            r0 = v.x; r1 = v.y; r2 = v.z; r3 = v.w;
        }
        atomicAdd(&g_deg[clampN(r0)], 1);
        atomicAdd(&g_deg[clampN(r1)], 1);
        atomicAdd(&g_deg[clampN(r2)], 1);
        atomicAdd(&g_deg[clampN(r3)], 1);
    }
}

// block-wise exclusive scan of g_deg (98 blocks x 1024)
__global__ void k_scanA() {
    __shared__ int s[1024];
    int tid = threadIdx.x;
    int i = blockIdx.x * 1024 + tid;
    int v = (i < N_NODES) ? g_deg[i] : 0;
    s[tid] = v;
    __syncthreads();
    for (int d = 1; d < 1024; d <<= 1) {
        int t = (tid >= d) ? s[tid - d] : 0;
        __syncthreads();
        s[tid] += t;
        __syncthreads();
    }
    if (i < N_NODES) g_off[i] = s[tid] - v;   // exclusive within block
    if (tid == 1023) g_bsum[blockIdx.x] = s[1023];
}

// scanC with inlined cross-block prefix: tree-reduce g_bsum[0..blockIdx.x)
__global__ void k_scanC() {
    __shared__ int red[128];
    int tid = threadIdx.x;
    if (tid < 128) red[tid] = (tid < blockIdx.x) ? g_bsum[tid] : 0; // blockIdx<=97
    __syncthreads();
#pragma unroll
    for (int d = 64; d > 0; d >>= 1) {
        if (tid < d) red[tid] += red[tid + d];
        __syncthreads();
    }
    int base = red[0];
    int i = blockIdx.x * 1024 + tid;
    if (i < N_NODES) {
        int o = g_off[i] + base;
        g_off[i] = o;
        g_cur[i] = o;
        g_dis[i] = rsqrtf((float)g_deg[i]);   // deg==0 -> inf, matches deg**-0.5
    }
}

// ---------------- scatter: 4 edges per thread, vector loads ----------------
__global__ void k_scatter(const void* __restrict__ eidx) {
    int q = blockIdx.x * blockDim.x + threadIdx.x;
    if (q < N_EDGES / 4) {
        int r[4], c[4];
        if (g_is64) {
            const longlong4* rp = (const longlong4*)eidx;
            const longlong4* cp = (const longlong4*)((const long long*)eidx + N_EDGES);
            longlong4 rv = rp[q], cv = cp[q];
            r[0] = (int)rv.x; r[1] = (int)rv.y; r[2] = (int)rv.z; r[3] = (int)rv.w;
            c[0] = (int)cv.x; c[1] = (int)cv.y; c[2] = (int)cv.z; c[3] = (int)cv.w;
        } else {
            const int4* rp = (const int4*)eidx;
            const int4* cp = (const int4*)((const int*)eidx + N_EDGES);
            int4 rv = rp[q], cv = cp[q];
            r[0] = rv.x; r[1] = rv.y; r[2] = rv.z; r[3] = rv.w;
            c[0] = cv.x; c[1] = cv.y; c[2] = cv.z; c[3] = cv.w;
        }
#pragma unroll
        for (int j = 0; j < 4; j++) {
            int pos = atomicAdd(&g_cur[clampN(r[j])], 1);
            g_scol[pos] = clampN(c[j]);
        }
    }
}

// ---------------- FP16 tensor-core dual GEMM (m16n8k16), resident weights -------
// out = x@Ws + bias (warps 0-15), g_h (fp16) = x@Wn (warps 16-31).
// Block: 128 rows, 1024 threads (32 warps). Each warp: 16 rows x 64 cols
// = 1 m-tile x 8 n-tiles of m16n8k16 over K=128 (8 k-steps).
// sX [r][k] half, stride 136; sW transposed [n][k] half, stride 136.
// u32-word stride = 68 = 4 (mod 32) -> frag banks 4*grp+tg, conflict-free.
#define XSH 136
#define WSH 136
#define GEMM_SMEM ((2 * 128 * WSH + 128 * XSH) * 2)   // 104448 B

__device__ __forceinline__ void mma_f16(float* d, const unsigned int* a,
                                        unsigned int b0, unsigned int b1) {
    asm("mma.sync.aligned.m16n8k16.row.col.f32.f16.f16.f32 "
        "{%0,%1,%2,%3}, {%4,%5,%6,%7}, {%8,%9}, {%0,%1,%2,%3};"
        : "+f"(d[0]), "+f"(d[1]), "+f"(d[2]), "+f"(d[3])
        : "r"(a[0]), "r"(a[1]), "r"(a[2]), "r"(a[3]), "r"(b0), "r"(b1));
}

__global__ void __launch_bounds__(1024)
k_gemm(const float* __restrict__ x,
       const float* __restrict__ Ws,
       const float* __restrict__ Wn,
       const float* __restrict__ bias,
       float* __restrict__ out) {
    extern __shared__ __half smem_h[];
    __half* sW = smem_h;                   // [mat*128+n][k] (transposed)
    __half* sX = smem_h + 2 * 128 * WSH;   // [r][k]

    int tid = threadIdx.x;
    int rowBase = blockIdx.x * 128;
    int warp = tid >> 5;
    int lane = tid & 31;
    int mat = warp >> 4;          // 0 = self(Ws->out), 1 = neighbor(Wn->g_h fp16)
    int ww = warp & 15;
    int rowOff = (ww >> 1) * 16;  // 0..112
    int colOff = (ww & 1) * 64;   // 0,64
    int grp = lane >> 2;          // 0..7
    int tg = lane & 3;            // 0..3

    // ---- stage weights transposed [n][k] as fp16 (coalesced LDG along n)
    for (int i = tid; i < 2 * 128 * 64; i += 1024) {   // 16384 half2 outputs
        int m  = i >> 13;
        int j  = i & 8191;
        int kp = j >> 7;          // k-pair 0..63
        int n  = j & 127;
        const float* Wm = m ? Wn : Ws;
        float v0 = Wm[(2 * kp)     * D + n];
        float v1 = Wm[(2 * kp + 1) * D + n];
        *(__half2*)&sW[(m * 128 + n) * WSH + 2 * kp] = __floats2half2_rn(v0, v1);
    }
    // ---- stage x tile [r][k] as fp16 (float4 loads)
    for (int i = tid; i < 128 * 32; i += 1024) {
        int r  = i >> 5;
        int kq = i & 31;
        int gr = rowBase + r;
        float4 v = (gr < N_NODES) ? ((const float4*)x)[(size_t)gr * 32 + kq]
                                  : make_float4(0.f, 0.f, 0.f, 0.f);
        *(__half2*)&sX[r * XSH + 4 * kq]     = __floats2half2_rn(v.x, v.y);
        *(__half2*)&sX[r * XSH + 4 * kq + 2] = __floats2half2_rn(v.z, v.w);
    }
    __syncthreads();

    float acc[8][4];
#pragma unroll
    for (int j = 0; j < 8; j++)
#pragma unroll
        for (int q = 0; q < 4; q++) acc[j][q] = 0.f;

    const __half* sWm = sW + mat * 128 * WSH;
    int r0l = rowOff + grp;
#pragma unroll
    for (int step = 0; step < 8; step++) {
        int k0 = step * 16;
        unsigned int a[4];
        a[0] = *(const unsigned int*)&sX[(r0l)     * XSH + k0 + 2 * tg];
        a[1] = *(const unsigned int*)&sX[(r0l + 8) * XSH + k0 + 2 * tg];
        a[2] = *(const unsigned int*)&sX[(r0l)     * XSH + k0 + 2 * tg + 8];
        a[3] = *(const unsigned int*)&sX[(r0l + 8) * XSH + k0 + 2 * tg + 8];
#pragma unroll
        for (int j = 0; j < 8; j++) {
            int n = colOff + 8 * j + grp;
            unsigned int b0 = *(const unsigned int*)&sWm[n * WSH + k0 + 2 * tg];
            unsigned int b1 = *(const unsigned int*)&sWm[n * WSH + k0 + 2 * tg + 8];
            mma_f16(acc[j], a, b0, b1);
        }
    }

    // epilogue: d0/d1 -> row grp, cols 2tg,2tg+1; d2/d3 -> row grp+8
    __half2* hview = (__half2*)g_h2;   // row-major: 64 half2 per row
#pragma unroll
    for (int j = 0; j < 8; j++) {
        int c = colOff + 8 * j + 2 * tg;
        int r0 = rowBase + rowOff + grp;
        int r1 = r0 + 8;
        if (mat == 0) {
            float2 bv = *(const float2*)&bias[c];
            if (r0 < N_NODES)
                *(float2*)&out[(size_t)r0 * D + c] =
                    make_float2(acc[j][0] + bv.x, acc[j][1] + bv.y);
            if (r1 < N_NODES)
                *(float2*)&out[(size_t)r1 * D + c] =
                    make_float2(acc[j][2] + bv.x, acc[j][3] + bv.y);
        } else {
            if (r0 < N_NODES)
                hview[(size_t)r0 * 64 + (c >> 1)] =
                    __floats2half2_rn(acc[j][0], acc[j][1]);
            if (r1 < N_NODES)
                hview[(size_t)r1 * 64 + (c >> 1)] =
                    __floats2half2_rn(acc[j][2], acc[j][3]);
        }
    }
}

// ---------------- SpMM: one warp per row, fp16 gather-accumulate (no atomics) ---
__global__ void __launch_bounds__(256)
k_spmm(float* __restrict__ out) {
    int gw = (blockIdx.x * blockDim.x + threadIdx.x) >> 5;
    int lane = threadIdx.x & 31;
    if (gw >= N_NODES) return;
    int r = gw;
    int beg = g_off[r];
    int cnt = g_deg[r];
    float disr = g_dis[r];

    float ax = 0.f, ay = 0.f, az = 0.f, aw = 0.f;
    int e = 0;
    for (; e + 1 < cnt; e += 2) {
        int c0 = g_scol[beg + e];
        int c1 = g_scol[beg + e + 1];
        float n0 = disr * g_dis[c0];
        float n1 = disr * g_dis[c1];
        uint2 v0 = g_h2[(size_t)c0 * 32 + lane];   // 4 halves = cols 4*lane..+3
        uint2 v1 = g_h2[(size_t)c1 * 32 + lane];
        float2 h0a = __half22float2(*(__half2*)&v0.x);
        float2 h0b = __half22float2(*(__half2*)&v0.y);
        float2 h1a = __half22float2(*(__half2*)&v1.x);
        float2 h1b = __half22float2(*(__half2*)&v1.y);
        ax += n0 * h0a.x + n1 * h1a.x;
        ay += n0 * h0a.y + n1 * h1a.y;
        az += n0 * h0b.x + n1 * h1b.x;
        aw += n0 * h0b.y + n1 * h1b.y;
    }
    if (e < cnt) {
        int c = g_scol[beg + e];
        float nrm = disr * g_dis[c];
        uint2 v = g_h2[(size_t)c * 32 + lane];
        float2 ha = __half22float2(*(__half2*)&v.x);
        float2 hb = __half22float2(*(__half2*)&v.y);
        ax += nrm * ha.x; ay += nrm * ha.y;
        az += nrm * hb.x; aw += nrm * hb.y;
    }
    float4* op = (float4*)out + (size_t)r * 32 + lane;
    float4 o = *op;               // already holds self_support + bias
    o.x += ax; o.y += ay; o.z += az; o.w += aw;
    *op = o;
}

// ---------------- launch: single stream ----------------
extern "C" void kernel_launch(void* const* d_in, const int* in_sizes, int n_in,
                              void* d_out, int out_size) {
    const float* x    = (const float*)d_in[0];
    const void*  eidx = d_in[1];                 // int32 or int64 — detected on device
    const float* Ws   = (const float*)d_in[2];
    const float* Wn   = (const float*)d_in[3];
    const float* bias = (const float*)d_in[4];
    float*       out  = (float*)d_out;

    cudaFuncSetAttribute(k_gemm, cudaFuncAttributeMaxDynamicSharedMemorySize,
                         GEMM_SMEM);

    k_zero_detect<<<(N_NODES + 255) / 256, 256>>>((const unsigned int*)eidx);
    k_count<<<(N_EDGES / 4 + 255) / 256, 256>>>(eidx);
    k_scanA<<<98, 1024>>>();
    k_scanC<<<98, 1024>>>();
    k_scatter<<<(N_EDGES / 4 + 255) / 256, 256>>>(eidx);
    k_gemm<<<(N_NODES + 127) / 128, 1024, GEMM_SMEM>>>(x, Ws, Wn, bias, out);
    k_spmm<<<(N_NODES * 32 + 255) / 256, 256>>>(out);
}